// round 1
// baseline (speedup 1.0000x reference)
#include <cuda_runtime.h>
#include <cuda_bf16.h>
#include <cstdint>

// ---------------------------------------------------------------------------
// Problem constants
// ---------------------------------------------------------------------------
#define T_STEPS   1024
#define BATCH     64
#define N_IN      256
#define N_HID     512
#define M_TOTAL   (T_STEPS * BATCH)       // 65536
#define YN        (BATCH * N_HID)         // 32768 state elements

#define GAIN_REC  0.04419417382415922f    // 1/sqrt(512)
#define DT_H      0.1f

// ---------------------------------------------------------------------------
// Scratch (device globals; no dynamic allocation allowed)
// ---------------------------------------------------------------------------
__device__ float    g_ext[(size_t)M_TOTAL * N_HID];   // 134 MB: inputs @ W_ih + b_ih
__device__ float    g_ybuf[2 * YN];                   // double-buffered y state
__device__ unsigned g_bar_cnt   = 0;                  // grid barrier counter
__device__ unsigned g_bar_phase = 0;                  // grid barrier phase

// ---------------------------------------------------------------------------
// Kernel A: ext = inputs @ W_ih + b_ih   (M=65536, N=512, K=256) fp32 tiled
// ---------------------------------------------------------------------------
#define TA_M 64
#define TA_N 64
#define TA_K 32

__global__ __launch_bounds__(256) void ext_gemm_kernel(
    const float* __restrict__ A,     // [M_TOTAL, 256]
    const float* __restrict__ W,     // [256, 512]
    const float* __restrict__ bias)  // [512]
{
    __shared__ float As[TA_K][TA_M + 4];   // [32][68] (k-major, padded)
    __shared__ float Bs[TA_K][TA_N];       // [32][64]

    const int tid = threadIdx.x;
    const int tx  = tid & 15;
    const int ty  = tid >> 4;
    const int m0  = blockIdx.y * TA_M;
    const int n0  = blockIdx.x * TA_N;

    float acc[4][4];
#pragma unroll
    for (int i = 0; i < 4; ++i)
#pragma unroll
        for (int j = 0; j < 4; ++j) acc[i][j] = 0.f;

    for (int kt = 0; kt < N_IN; kt += TA_K) {
        // Load A tile 64x32 (512 float4, 2 per thread), store transposed
#pragma unroll
        for (int j = 0; j < 2; ++j) {
            int f  = tid + j * 256;          // 0..511
            int r  = f >> 3;                 // 0..63
            int c4 = f & 7;                  // 0..7
            float4 v = *(const float4*)&A[(size_t)(m0 + r) * N_IN + kt + c4 * 4];
            As[c4 * 4 + 0][r] = v.x;
            As[c4 * 4 + 1][r] = v.y;
            As[c4 * 4 + 2][r] = v.z;
            As[c4 * 4 + 3][r] = v.w;
        }
        // Load B tile 32x64 (512 float4, 2 per thread)
#pragma unroll
        for (int j = 0; j < 2; ++j) {
            int f  = tid + j * 256;
            int r  = f >> 4;                 // 0..31
            int c4 = f & 15;                 // 0..15
            *(float4*)&Bs[r][c4 * 4] =
                *(const float4*)&W[(size_t)(kt + r) * N_HID + n0 + c4 * 4];
        }
        __syncthreads();

#pragma unroll
        for (int k = 0; k < TA_K; ++k) {
            float a[4], bb[4];
            *(float4*)a  = *(const float4*)&As[k][ty * 4];
            *(float4*)bb = *(const float4*)&Bs[k][tx * 4];
#pragma unroll
            for (int i = 0; i < 4; ++i)
#pragma unroll
                for (int j = 0; j < 4; ++j)
                    acc[i][j] = fmaf(a[i], bb[j], acc[i][j]);
        }
        __syncthreads();
    }

    // Epilogue: add bias, write g_ext
    float4 bv = *(const float4*)&bias[n0 + tx * 4];
#pragma unroll
    for (int i = 0; i < 4; ++i) {
        int m = m0 + ty * 4 + i;
        float4 o;
        o.x = acc[i][0] + bv.x;
        o.y = acc[i][1] + bv.y;
        o.z = acc[i][2] + bv.z;
        o.w = acc[i][3] + bv.w;
        *(float4*)&g_ext[(size_t)m * N_HID + n0 + tx * 4] = o;
    }
}

// ---------------------------------------------------------------------------
// Kernel B: persistent recurrence over T=1024 steps
//   grid = 128 CTAs x 256 threads; CTA c owns 4 output columns (all 64 batches)
//   W_hh slice (512x4) cached in SMEM; full y re-staged to SMEM each step.
// ---------------------------------------------------------------------------
#define NB 128
#define NT 256
// SMEM layout (floats): ys[64][516] then ws[128][4] (float4 interleaved)
#define YS_STRIDE4 129                      // 516 floats = 129 float4 per row
#define YS_FLOATS  (64 * 516)               // 33024
#define WS_FLOATS  (128 * 16)               // 2048
#define SMEM_B_BYTES ((YS_FLOATS + WS_FLOATS) * 4)   // 140288

__global__ __launch_bounds__(NT, 1) void horn_rec_kernel(
    const float* __restrict__ W_hh,
    const float* __restrict__ b_hh,
    const float* __restrict__ alpha,
    const float* __restrict__ omega,
    const float* __restrict__ gamma,
    const float* __restrict__ vvec,
    float* __restrict__ out)
{
    extern __shared__ float smem[];
    float4* ys4 = (float4*)smem;                  // [64][129] float4
    float4* ws4 = (float4*)(smem + YS_FLOATS);    // [k4][hl] float4

    const int tid = threadIdx.x;
    const int b   = tid >> 2;                     // 0..63
    const int hl  = tid & 3;                      // 0..3
    const int h   = blockIdx.x * 4 + hl;          // global hidden column

    // Cache W_hh[:, 4 columns] into SMEM as ws4[k4][hl] (element k -> .x..w)
    {
        float* wsf = smem + YS_FLOATS;
        for (int idx = tid; idx < 4 * N_HID; idx += NT) {
            int k = idx >> 2;
            int l = idx & 3;
            wsf[(k >> 2) * 16 + l * 4 + (k & 3)] =
                W_hh[(size_t)k * N_HID + blockIdx.x * 4 + l];
        }
    }

    // Per-thread parameters
    const float bhh = __ldg(&b_hh[h]);
    const float al  = __ldg(&alpha[h]);
    const float om  = __ldg(&omega[h]);
    const float om2 = om * om;
    const float g2  = 2.f * __ldg(&gamma[h]);
    const float vv  = __ldg(&vvec[h]);

    // Read barrier phase base (before any arrival anywhere -> safe)
    __shared__ unsigned sbase;
    if (tid == 0) sbase = *(volatile unsigned*)&g_bar_phase;
    __syncthreads();                              // also covers ws4 fill
    const unsigned base = sbase;

    float x = 0.f, y = 0.f;
    const float* extp = g_ext + (size_t)b * N_HID + h;
    float*       outp = out   + (size_t)b * N_HID + h;

    for (int t = 0; t < T_STEPS; ++t) {
        float e   = __ldg(extp + (size_t)t * YN);
        float acc = 0.f;

        if (t > 0) {
            // Stage full y (prev step) into SMEM, L1-bypassing loads
            const float4* src = (const float4*)(g_ybuf + (size_t)(t & 1) * YN);
#pragma unroll
            for (int j = 0; j < 32; ++j) {
                int g = j * NT + tid;             // 0..8191 float4 index
                float4 v = __ldcg(src + g);
                ys4[(g >> 7) * YS_STRIDE4 + (g & 127)] = v;
            }
            __syncthreads();

            // Dot: rec[b][h] = sum_k y[b][k] * W_hh[k][h]
            const float4* ysp = ys4 + b * YS_STRIDE4;
            float a0 = 0.f, a1 = 0.f, a2 = 0.f, a3 = 0.f;
#pragma unroll 8
            for (int k4 = 0; k4 < 128; ++k4) {
                float4 yv = ysp[k4];
                float4 wv = ws4[k4 * 4 + hl];
                a0 = fmaf(yv.x, wv.x, a0);
                a1 = fmaf(yv.y, wv.y, a1);
                a2 = fmaf(yv.z, wv.z, a2);
                a3 = fmaf(yv.w, wv.w, a3);
            }
            acc = (a0 + a1) + (a2 + a3);
        }

        // Elementwise HORN dynamics
        float inp = e + GAIN_REC * (acc + bhh + vv * x);
        float yn  = fmaf(DT_H, al * tanhf(inp) - om2 * x - g2 * y, y);
        float xn  = fmaf(DT_H, yn, x);
        x = xn; y = yn;

        __stcg(&g_ybuf[(size_t)((t + 1) & 1) * YN + (size_t)b * N_HID + h], yn);
        outp[(size_t)t * YN] = xn;

        // ---- grid barrier (sense via monotone phase) ----
        __threadfence();           // make st.cg visible before arrival
        __syncthreads();
        if (tid == 0) {
            unsigned old = atomicInc(&g_bar_cnt, NB - 1u);   // wraps to 0
            if (old == NB - 1u) {
                atomicExch(&g_bar_phase, base + (unsigned)(t + 1));
            } else {
                while (*(volatile unsigned*)&g_bar_phase < base + (unsigned)(t + 1))
                    __nanosleep(32);
            }
            __threadfence();
        }
        __syncthreads();
    }
}

// ---------------------------------------------------------------------------
// Launch
// ---------------------------------------------------------------------------
extern "C" void kernel_launch(void* const* d_in, const int* in_sizes, int n_in,
                              void* d_out, int out_size)
{
    const float* inputs = (const float*)d_in[0];   // [1024,64,256]
    const float* W_ih   = (const float*)d_in[1];   // [256,512]
    const float* b_ih   = (const float*)d_in[2];   // [512]
    const float* W_hh   = (const float*)d_in[3];   // [512,512]
    const float* b_hh   = (const float*)d_in[4];   // [512]
    const float* alpha  = (const float*)d_in[5];   // [512]
    const float* omega  = (const float*)d_in[6];   // [512]
    const float* gamma  = (const float*)d_in[7];   // [512]
    const float* v      = (const float*)d_in[8];   // [512]
    float* out = (float*)d_out;                    // [1024,64,512]

    (void)in_sizes; (void)n_in; (void)out_size;

    cudaFuncSetAttribute(horn_rec_kernel,
                         cudaFuncAttributeMaxDynamicSharedMemorySize,
                         SMEM_B_BYTES);

    dim3 gA(N_HID / TA_N, M_TOTAL / TA_M);         // (8, 1024)
    ext_gemm_kernel<<<gA, 256>>>(inputs, W_ih, b_ih);

    horn_rec_kernel<<<NB, NT, SMEM_B_BYTES>>>(W_hh, b_hh, alpha, omega,
                                              gamma, v, out);
}

// round 2
// speedup vs baseline: 1.1611x; 1.1611x over previous
#include <cuda_runtime.h>
#include <cuda_bf16.h>
#include <cstdint>

// ---------------------------------------------------------------------------
// Problem constants
// ---------------------------------------------------------------------------
#define T_STEPS   1024
#define BATCH     64
#define N_IN      256
#define N_HID     512
#define M_TOTAL   (T_STEPS * BATCH)       // 65536
#define YN        (BATCH * N_HID)         // 32768 state elements

#define GAIN_REC  0.04419417382415922f    // 1/sqrt(512)
#define DT_H      0.1f

// ---------------------------------------------------------------------------
// Scratch (device globals; no dynamic allocation allowed)
// ---------------------------------------------------------------------------
__device__ float    g_ext[(size_t)M_TOTAL * N_HID];   // 134 MB: inputs @ W_ih + b_ih
__device__ float    g_ybuf[2 * YN];                   // double-buffered y state
__device__ unsigned g_bar_cnt   = 0;                  // grid barrier counter (mod NB)
__device__ unsigned g_bar_phase = 0;                  // monotone phase

// ---------------------------------------------------------------------------
// Kernel A: ext = inputs @ W_ih + b_ih   (M=65536, N=512, K=256) fp32 tiled
// ---------------------------------------------------------------------------
#define TA_M 64
#define TA_N 64
#define TA_K 32

__global__ __launch_bounds__(256) void ext_gemm_kernel(
    const float* __restrict__ A,     // [M_TOTAL, 256]
    const float* __restrict__ W,     // [256, 512]
    const float* __restrict__ bias)  // [512]
{
    __shared__ float As[TA_K][TA_M + 4];   // [32][68] (k-major, padded)
    __shared__ float Bs[TA_K][TA_N];       // [32][64]

    const int tid = threadIdx.x;
    const int tx  = tid & 15;
    const int ty  = tid >> 4;
    const int m0  = blockIdx.y * TA_M;
    const int n0  = blockIdx.x * TA_N;

    float acc[4][4];
#pragma unroll
    for (int i = 0; i < 4; ++i)
#pragma unroll
        for (int j = 0; j < 4; ++j) acc[i][j] = 0.f;

    for (int kt = 0; kt < N_IN; kt += TA_K) {
#pragma unroll
        for (int j = 0; j < 2; ++j) {
            int f  = tid + j * 256;          // 0..511
            int r  = f >> 3;                 // 0..63
            int c4 = f & 7;                  // 0..7
            float4 v = *(const float4*)&A[(size_t)(m0 + r) * N_IN + kt + c4 * 4];
            As[c4 * 4 + 0][r] = v.x;
            As[c4 * 4 + 1][r] = v.y;
            As[c4 * 4 + 2][r] = v.z;
            As[c4 * 4 + 3][r] = v.w;
        }
#pragma unroll
        for (int j = 0; j < 2; ++j) {
            int f  = tid + j * 256;
            int r  = f >> 4;                 // 0..31
            int c4 = f & 15;                 // 0..15
            *(float4*)&Bs[r][c4 * 4] =
                *(const float4*)&W[(size_t)(kt + r) * N_HID + n0 + c4 * 4];
        }
        __syncthreads();

#pragma unroll
        for (int k = 0; k < TA_K; ++k) {
            float a[4], bb[4];
            *(float4*)a  = *(const float4*)&As[k][ty * 4];
            *(float4*)bb = *(const float4*)&Bs[k][tx * 4];
#pragma unroll
            for (int i = 0; i < 4; ++i)
#pragma unroll
                for (int j = 0; j < 4; ++j)
                    acc[i][j] = fmaf(a[i], bb[j], acc[i][j]);
        }
        __syncthreads();
    }

    float4 bv = *(const float4*)&bias[n0 + tx * 4];
#pragma unroll
    for (int i = 0; i < 4; ++i) {
        int m = m0 + ty * 4 + i;
        float4 o;
        o.x = acc[i][0] + bv.x;
        o.y = acc[i][1] + bv.y;
        o.z = acc[i][2] + bv.z;
        o.w = acc[i][3] + bv.w;
        *(float4*)&g_ext[(size_t)m * N_HID + n0 + tx * 4] = o;
    }
}

// ---------------------------------------------------------------------------
// Kernel B: persistent recurrence over T=1024 steps
//   128 CTAs laid out as 4 batch-groups x 32 hidden-groups.
//   Each CTA owns a 16b x 16h output tile; stages only its 16 y-rows (32 KB).
//   W_hh slice (512x16) cached in SMEM. Grid barrier per step.
// ---------------------------------------------------------------------------
#define NB 128
#define NT 256

#define YS_STRIDE4 129                       // float4 stride per y row (pad)
#define YS_FLOATS  (16 * 516)                // 8256 floats
#define WS_FLOATS  (128 * 16 * 4)            // 8192 floats
#define SMEM_B_BYTES ((YS_FLOATS + WS_FLOATS) * 4)   // 65792 bytes

__device__ __forceinline__ void cp_async16(uint32_t dst_smem, const void* src) {
    asm volatile("cp.async.cg.shared.global [%0], [%1], 16;\n"
                 :: "r"(dst_smem), "l"(src) : "memory");
}

__global__ __launch_bounds__(NT, 1) void horn_rec_kernel(
    const float* __restrict__ W_hh,
    const float* __restrict__ b_hh,
    const float* __restrict__ alpha,
    const float* __restrict__ omega,
    const float* __restrict__ gamma,
    const float* __restrict__ vvec,
    float* __restrict__ out)
{
    extern __shared__ float smem[];
    float4* ys4 = (float4*)smem;                  // [16][129] float4
    float4* ws4 = (float4*)(smem + YS_FLOATS);    // [k4][16] float4

    const int tid  = threadIdx.x;
    const int bg   = blockIdx.x & 3;              // batch group (4)
    const int hg   = blockIdx.x >> 2;             // hidden group (32)
    const int wid  = tid >> 5;
    const int lane = tid & 31;
    const int bl   = (wid & 1) * 8 + (lane >> 2); // local b 0..15
    const int hl   = (wid >> 1) * 4 + (lane & 3); // local h 0..15
    const int b    = bg * 16 + bl;
    const int h    = hg * 16 + hl;

    // Cache W_hh[:, 16 columns] into SMEM: ws4[k4*16 + l] = W[4k4..4k4+3][hg*16+l]
    {
        float* wsf = smem + YS_FLOATS;
        for (int idx = tid; idx < 16 * N_HID; idx += NT) {
            int k = idx >> 4;
            int l = idx & 15;
            wsf[(k >> 2) * 64 + l * 4 + (k & 3)] =
                W_hh[(size_t)k * N_HID + hg * 16 + l];
        }
    }

    // Per-thread parameters
    const float bhh = __ldg(&b_hh[h]);
    const float al  = __ldg(&alpha[h]);
    const float om  = __ldg(&omega[h]);
    const float om2 = om * om;
    const float g2  = 2.f * __ldg(&gamma[h]);
    const float vv  = __ldg(&vvec[h]);

    // Read monotone phase base (before this CTA's first arrival -> race-free)
    __shared__ unsigned sbase;
    if (tid == 0) {
        unsigned p;
        asm volatile("ld.acquire.gpu.global.u32 %0, [%1];"
                     : "=r"(p) : "l"(&g_bar_phase) : "memory");
        sbase = p;
    }
    __syncthreads();                              // also covers ws4 fill
    const unsigned base = sbase;

    float x = 0.f, y = 0.f;
    const float* extp = g_ext + (size_t)b * N_HID + h;
    float*       outp = out   + (size_t)b * N_HID + h;

    const uint32_t ys_smem = (uint32_t)__cvta_generic_to_shared(ys4);
    const float4*  ysp     = ys4 + bl * YS_STRIDE4;
    const float4*  wsp     = ws4 + hl;

    for (int t = 0; t < T_STEPS; ++t) {
        float e   = __ldcg((float*)(extp + (size_t)t * YN));
        float acc = 0.f;

        if (t > 0) {
            // Stage this CTA's 16 y rows (2048 float4) via cp.async (L2 path)
            const float4* src = (const float4*)(g_ybuf + (size_t)(t & 1) * YN)
                              + (size_t)bg * 16 * 128;
#pragma unroll
            for (int j = 0; j < 8; ++j) {
                int g = j * NT + tid;             // 0..2047
                int r = g >> 7;
                int c = g & 127;
                cp_async16(ys_smem + (uint32_t)(r * YS_STRIDE4 + c) * 16,
                           src + g);
            }
            asm volatile("cp.async.commit_group;\n" ::: "memory");
            asm volatile("cp.async.wait_group 0;\n" ::: "memory");
            __syncthreads();

            // Dot: rec[b][h] = sum_k y[b][k] * W_hh[k][h]
            float a0 = 0.f, a1 = 0.f, a2 = 0.f, a3 = 0.f;
#pragma unroll 16
            for (int k4 = 0; k4 < 128; ++k4) {
                float4 yv = ysp[k4];
                float4 wv = wsp[k4 * 16];
                a0 = fmaf(yv.x, wv.x, a0);
                a1 = fmaf(yv.y, wv.y, a1);
                a2 = fmaf(yv.z, wv.z, a2);
                a3 = fmaf(yv.w, wv.w, a3);
            }
            acc = (a0 + a1) + (a2 + a3);
        }

        // Elementwise HORN dynamics
        float inp = e + GAIN_REC * (acc + bhh + vv * x);
        float yn  = fmaf(DT_H, al * tanhf(inp) - om2 * x - g2 * y, y);
        float xn  = fmaf(DT_H, yn, x);
        x = xn; y = yn;

        __stcg(&g_ybuf[(size_t)((t + 1) & 1) * YN + (size_t)b * N_HID + h], yn);
        outp[(size_t)t * YN] = xn;

        // ---- grid barrier: one release-arrival per CTA, acquire-poll ----
        __syncthreads();
        if (tid == 0) {
            unsigned old;
            asm volatile("atom.acq_rel.gpu.global.inc.u32 %0, [%1], %2;"
                         : "=r"(old) : "l"(&g_bar_cnt), "r"(NB - 1u) : "memory");
            unsigned target = base + (unsigned)(t + 1);
            if (old == NB - 1u) {
                asm volatile("st.release.gpu.global.u32 [%0], %1;"
                             :: "l"(&g_bar_phase), "r"(target) : "memory");
            } else {
                unsigned cur;
                do {
                    asm volatile("ld.acquire.gpu.global.u32 %0, [%1];"
                                 : "=r"(cur) : "l"(&g_bar_phase) : "memory");
                } while ((cur - base) < (unsigned)(t + 1));
            }
        }
        __syncthreads();
    }
}

// ---------------------------------------------------------------------------
// Launch
// ---------------------------------------------------------------------------
extern "C" void kernel_launch(void* const* d_in, const int* in_sizes, int n_in,
                              void* d_out, int out_size)
{
    const float* inputs = (const float*)d_in[0];   // [1024,64,256]
    const float* W_ih   = (const float*)d_in[1];   // [256,512]
    const float* b_ih   = (const float*)d_in[2];   // [512]
    const float* W_hh   = (const float*)d_in[3];   // [512,512]
    const float* b_hh   = (const float*)d_in[4];   // [512]
    const float* alpha  = (const float*)d_in[5];   // [512]
    const float* omega  = (const float*)d_in[6];   // [512]
    const float* gamma  = (const float*)d_in[7];   // [512]
    const float* v      = (const float*)d_in[8];   // [512]
    float* out = (float*)d_out;                    // [1024,64,512]

    (void)in_sizes; (void)n_in; (void)out_size;

    cudaFuncSetAttribute(horn_rec_kernel,
                         cudaFuncAttributeMaxDynamicSharedMemorySize,
                         SMEM_B_BYTES);

    dim3 gA(N_HID / TA_N, M_TOTAL / TA_M);         // (8, 1024)
    ext_gemm_kernel<<<gA, 256>>>(inputs, W_ih, b_ih);

    horn_rec_kernel<<<NB, NT, SMEM_B_BYTES>>>(W_hh, b_hh, alpha, omega,
                                              gamma, v, out);
}